// round 8
// baseline (speedup 1.0000x reference)
#include <cuda_runtime.h>
#include <math.h>

#define GN     6
#define NCELL  36
#define HID    128
#define NT     64      // threads per block (pair kernel)
#define APB    (2*NT)  // agents per block = 128 (2 per thread)
#define SEG    32      // j-segments -> grid 2048 when N=8192; TJ==JS: one tile/segment
#define TJ     256     // j tile size (== 8192/SEG when N==MAXN)
#define MAXN   8192
#define BI     32      // rows per block in GEMM kernel

// Partial occupancy planes, uint16: [seg][cell][i] (count per segment <= TJ=256)
__device__ unsigned short g_part[SEG * NCELL * MAXN];
// Reduced occupancy, transposed float: [cell][i]
__device__ float g_occ[NCELL * MAXN];

// rx, ry are precombined grid coords (tile holds 2*xj+3; thread holds -2*xi;
// one FADD joins them). Invalid agents carry +1e30 -> rx huge -> F2I saturates
// -> unsigned range check fails -> trash row (branchless).
// Histogram is uint32, conflict-free (bank = tid%32). Agent A counts live in
// the low 16 bits (inc=1), agent B in the high 16 bits (inc=1<<16); per-segment
// counts <= TJ=256 so halves never carry into each other.
__device__ __forceinline__ void bump(unsigned* occ, int tid, float rx, float ry,
                                     unsigned inc, int trash) {
    int ix = __float2int_rd(rx);
    int iy = __float2int_rd(ry);
    int cell = ix * GN + iy;
    bool ok = ((unsigned)ix < (unsigned)GN) & ((unsigned)iy < (unsigned)GN);
    cell = ok ? cell : trash;
    occ[cell * NT + tid] += inc;
}

template<bool EXACT>
__global__ __launch_bounds__(NT, 16)
void occ_pair_kernel(const float2* __restrict__ obs, int N) {
    __shared__ __align__(16) float2 tile[TJ];        // holds (2*xj+3, 2*yj+3)
    __shared__ unsigned occ[(NCELL + 2) * NT];       // rows 36 (A) / 37 (B) = trash

    const int tid = threadIdx.x;
    const int iA  = blockIdx.x * APB + tid;
    const int iB  = iA + NT;
    const int seg = blockIdx.y;
    const int JS  = EXACT ? (MAXN / SEG) : ((N + SEG - 1) / SEG);
    const int j0  = seg * JS;
    const int j1  = EXACT ? (j0 + JS) : min(j0 + JS, N);

    // Hold -2*x_i (exact: *2 exact, negate exact). Invalid -> +1e30 sentinel.
    float nxA = 1e30f, nyA = 1e30f, nxB = 1e30f, nyB = 1e30f;
    if (iA < N) {
        float2 p = obs[iA];
        if (!isnan(p.x) && !isnan(p.y)) { nxA = -2.0f * p.x; nyA = -2.0f * p.y; }
    }
    if (iB < N) {
        float2 p = obs[iB];
        if (!isnan(p.x) && !isnan(p.y)) { nxB = -2.0f * p.x; nyB = -2.0f * p.y; }
    }

    #pragma unroll
    for (int c = 0; c < NCELL + 2; c++) occ[c * NT + tid] = 0;
    __syncthreads();

    for (int jb = j0; jb < j1; jb += TJ) {
        const int nj = EXACT ? TJ : min(TJ, j1 - jb);
        for (int t = tid; t < nj; t += NT) {
            float2 p = obs[jb + t];
            float2 v;
            if (isnan(p.x) || isnan(p.y)) { v.x = 1e30f; v.y = 1e30f; }
            else { v.x = fmaf(p.x, 2.0f, 3.0f); v.y = fmaf(p.y, 2.0f, 3.0f); }
            tile[t] = v;
        }
        __syncthreads();

        // Two j's per LDS.128 broadcast; one FADD per coordinate per pair.
        const float4* t4 = (const float4*)tile;
        const int nj2 = nj >> 1;
        #pragma unroll 4
        for (int jj = 0; jj < nj2; jj++) {
            const float4 q = t4[jj];
            bump(occ, tid, q.x + nxA, q.y + nyA, 1u,        NCELL);
            bump(occ, tid, q.x + nxB, q.y + nyB, 1u << 16,  NCELL + 1);
            bump(occ, tid, q.z + nxA, q.w + nyA, 1u,        NCELL);
            bump(occ, tid, q.z + nxB, q.w + nyB, 1u << 16,  NCELL + 1);
        }
        if (!EXACT && (nj & 1)) {
            const float2 p = tile[nj - 1];
            bump(occ, tid, p.x + nxA, p.y + nyA, 1u,       NCELL);
            bump(occ, tid, p.x + nxB, p.y + nyB, 1u << 16, NCELL + 1);
        }
        __syncthreads();
    }

    if (iA < N) {
        #pragma unroll
        for (int c = 0; c < NCELL; c++)
            g_part[(seg * NCELL + c) * N + iA] = (unsigned short)(occ[c * NT + tid] & 0xFFFFu);
    }
    if (iB < N) {
        #pragma unroll
        for (int c = 0; c < NCELL; c++)
            g_part[(seg * NCELL + c) * N + iB] = (unsigned short)(occ[c * NT + tid] >> 16);
    }
}

// Segment reduction: one thread per (cell, 8 agents); packed uint16 adds.
__global__ __launch_bounds__(256)
void occ_reduce_kernel(int N) {
    const int nI8 = N >> 3;
    const int t   = blockIdx.x * 256 + threadIdx.x;
    if (t >= NCELL * nI8) return;
    const int c = t / nI8;
    const int i = (t - c * nI8) * 8;

    uint4 acc = make_uint4(0u, 0u, 0u, 0u);
    #pragma unroll
    for (int sg = 0; sg < SEG; sg++) {
        const uint4 v = *reinterpret_cast<const uint4*>(
            &g_part[(sg * NCELL + c) * N + i]);          // 8 uint16 per LDG.128
        acc.x = __vadd2(acc.x, v.x);                     // sums <= N < 2^16
        acc.y = __vadd2(acc.y, v.y);
        acc.z = __vadd2(acc.z, v.z);
        acc.w = __vadd2(acc.w, v.w);
    }
    float4 lo, hi;
    lo.x = (float)(acc.x & 0xFFFFu); lo.y = (float)(acc.x >> 16);
    lo.z = (float)(acc.y & 0xFFFFu); lo.w = (float)(acc.y >> 16);
    hi.x = (float)(acc.z & 0xFFFFu); hi.y = (float)(acc.z >> 16);
    hi.z = (float)(acc.w & 0xFFFFu); hi.w = (float)(acc.w >> 16);
    *reinterpret_cast<float4*>(&g_occ[c * N + i])     = lo;
    *reinterpret_cast<float4*>(&g_occ[c * N + i + 4]) = hi;
}

// Generic-N fallback reduction (scalar).
__global__ __launch_bounds__(256)
void occ_reduce_generic(int N) {
    const int t = blockIdx.x * 256 + threadIdx.x;
    if (t >= NCELL * N) return;
    const int c = t / N;
    const int i = t - c * N;
    unsigned s = 0;
    #pragma unroll
    for (int sg = 0; sg < SEG; sg++)
        s += g_part[(sg * NCELL + c) * N + i];
    g_occ[c * N + i] = (float)s;
}

// [N,36] x [36,128] GEMM with smem-staged W and broadcast occ reads.
__global__ __launch_bounds__(256)
void occ_gemm_kernel(const float2* __restrict__ obs,
                     const float*  __restrict__ W,
                     const float*  __restrict__ b,
                     float*        __restrict__ out, int N) {
    __shared__ float sW[HID * 37];                   // stride 37: 5h+c mod 32 conflict-free
    __shared__ __align__(16) float occ_s[BI][40];    // row stride 40: float4-aligned
    __shared__ float sself[BI];

    const int tid = threadIdx.x;
    const int i0  = blockIdx.x * BI;

    // Stage W coalesced.
    for (int idx = tid; idx < HID * NCELL; idx += 256) {
        const int h = idx / NCELL;
        sW[h * 37 + (idx - h * NCELL)] = W[idx];
    }
    // Load occ tile (coalesced along i from the [cell][i] layout).
    for (int idx = tid; idx < NCELL * BI; idx += 256) {
        const int c = idx >> 5, l = idx & 31;
        const int i = i0 + l;
        occ_s[l][c] = (i < N) ? g_occ[c * N + i] : 0.f;
    }
    if (tid < BI) {
        const int i = i0 + tid;
        float v = 0.f;
        if (i < N) {
            const float2 p = obs[i];
            if (!isnan(p.x) && !isnan(p.y)) v = 1.f;
        }
        sself[tid] = v;
    }
    __syncthreads();

    const int h = tid & (HID - 1);
    float w[NCELL];
    #pragma unroll
    for (int c = 0; c < NCELL; c++) w[c] = sW[h * 37 + c];
    const float bias = b[h];

    const int il0 = (tid >> 7) * (BI / 2);
    #pragma unroll
    for (int r = 0; r < BI / 2; r++) {
        const int il = il0 + r;
        const int i  = i0 + il;
        if (i >= N) break;
        // Self-pair was counted at cell 21 iff agent i is finite; remove it.
        float acc = fmaf(-sself[il], w[21], bias);
        const float4* row = (const float4*)&occ_s[il][0];
        #pragma unroll
        for (int c4 = 0; c4 < 9; c4++) {
            const float4 v = row[c4];     // broadcast LDS.128
            acc = fmaf(v.x, w[c4 * 4 + 0], acc);
            acc = fmaf(v.y, w[c4 * 4 + 1], acc);
            acc = fmaf(v.z, w[c4 * 4 + 2], acc);
            acc = fmaf(v.w, w[c4 * 4 + 3], acc);
        }
        out[i * HID + h] = acc;
    }
}

extern "C" void kernel_launch(void* const* d_in, const int* in_sizes, int n_in,
                              void* d_out, int out_size) {
    const float2* obs = (const float2*)d_in[0];
    const float*  W   = (const float*)d_in[1];
    const float*  b   = (const float*)d_in[2];
    float*        out = (float*)d_out;
    const int N = in_sizes[0] / 2;

    if (N == MAXN) {
        dim3 g1(MAXN / APB, SEG);
        occ_pair_kernel<true><<<g1, NT>>>(obs, N);
    } else {
        dim3 g1((N + APB - 1) / APB, SEG);
        occ_pair_kernel<false><<<g1, NT>>>(obs, N);
    }
    if ((N & 7) == 0) {
        const int rthreads = NCELL * (N >> 3);
        occ_reduce_kernel<<<(rthreads + 255) / 256, 256>>>(N);
    } else {
        const int rthreads = NCELL * N;
        occ_reduce_generic<<<(rthreads + 255) / 256, 256>>>(N);
    }
    occ_gemm_kernel<<<(N + BI - 1) / BI, 256>>>(obs, W, b, out, N);
}